// round 3
// baseline (speedup 1.0000x reference)
#include <cuda_runtime.h>
#include <cuda_bf16.h>
#include <mma.h>
#include <cstdint>

using namespace nvcuda;

constexpr int NWIN = 8, CH = 1024, C2 = 512;
constexpr int SLAB = 256, WINSLABS = 6;
constexpr int ROWS_TOTAL = NWIN * WINSLABS * SLAB;      // 12288
constexpr int GUARD = SLAB;
constexpr int ROWS_ALLOC = ROWS_TOTAL + 2 * GUARD;      // 12800
constexpr int KDIM = 27 * CH;                           // 27648
constexpr int BM = 128, BN = 128, BK = 32;
constexpr int LDA = 48, LDB = 144, LDSTG = 132;
constexpr int SMEM_BYTES = (2 * BM * LDA + 2 * BK * LDB) * 2 * 2; // 86016

__device__ __nv_bfloat16 g_X1h[(size_t)ROWS_ALLOC * CH];
__device__ __nv_bfloat16 g_X1l[(size_t)ROWS_ALLOC * CH];
__device__ __nv_bfloat16 g_X2h[(size_t)ROWS_ALLOC * CH];
__device__ __nv_bfloat16 g_X2l[(size_t)ROWS_ALLOC * CH];
__device__ __nv_bfloat16 g_W1Th[(size_t)KDIM * CH];
__device__ __nv_bfloat16 g_W1Tl[(size_t)KDIM * CH];
__device__ __nv_bfloat16 g_W2Th[(size_t)KDIM * C2];
__device__ __nv_bfloat16 g_W2Tl[(size_t)KDIM * C2];
__device__ float g_pooled[NWIN * C2];
__device__ float g_m1[NWIN * 512];
__device__ float g_m2[NWIN * 512];

__device__ __forceinline__ void split_bf16(float v, __nv_bfloat16& hi, __nv_bfloat16& lo) {
    hi = __float2bfloat16(v);
    lo = __float2bfloat16(v - __bfloat162float(hi));
}

__global__ void k_zero_pooled() {
    int i = blockIdx.x * 256 + threadIdx.x;
    if (i < NWIN * C2) g_pooled[i] = 0.f;
}

// videos (1,8,1024,14,14) -> padded channels-last windows, hi/lo split
__global__ void k_gather(const float* __restrict__ videos) {
    int i = blockIdx.x * 256 + threadIdx.x;
    constexpr int TOT = NWIN * 4 * 14 * 14 * CH;
    if (i >= TOT) return;
    int c = i & (CH - 1);
    int rest = i >> 10;
    int w = rest % 14; rest /= 14;
    int h = rest % 14; rest /= 14;
    int d = rest & 3;
    int t = rest >> 2;
    int frame = t - 4 + d;  // window t holds frames t-4..t-1 (zeros before 0)
    float v = (frame >= 0) ? videos[(size_t)(frame * CH + c) * 196 + h * 14 + w] : 0.f;
    __nv_bfloat16 hi, lo; split_bf16(v, hi, lo);
    size_t dst = (size_t)(GUARD + (t * WINSLABS + d + 1) * SLAB + (h + 1) * 16 + (w + 1)) * CH + c;
    g_X1h[dst] = hi;
    g_X1l[dst] = lo;
}

// conv weights (oc, ic, 27) -> WT[kidx*CH+ic][oc] hi/lo
template<int NOC>
__global__ void k_transpose(const float* __restrict__ w,
                            __nv_bfloat16* __restrict__ wth,
                            __nv_bfloat16* __restrict__ wtl) {
    __shared__ float s[32][28];
    int ocBase = blockIdx.x * 32;
    int ic = blockIdx.y;
    for (int idx = threadIdx.x; idx < 32 * 27; idx += 256) {
        int oc = idx / 27, kk = idx - oc * 27;
        s[oc][kk] = w[((size_t)(ocBase + oc) * CH + ic) * 27 + kk];
    }
    __syncthreads();
    for (int idx = threadIdx.x; idx < 27 * 32; idx += 256) {
        int kk = idx >> 5, oc = idx & 31;
        __nv_bfloat16 hi, lo; split_bf16(s[oc][kk], hi, lo);
        size_t o = ((size_t)kk * CH + ic) * NOC + ocBase + oc;
        wth[o] = hi;
        wtl[o] = lo;
    }
}

// Implicit-conv GEMM, bf16 hi/lo 3-term, 128x128x32 tiles, 8 warps.
template<int N, bool POOL>
__global__ void __launch_bounds__(256)
k_gemm(const float* __restrict__ bias) {
    const __nv_bfloat16* __restrict__ Xh = (POOL ? g_X2h : g_X1h) + (size_t)GUARD * CH;
    const __nv_bfloat16* __restrict__ Xl = (POOL ? g_X2l : g_X1l) + (size_t)GUARD * CH;
    const __nv_bfloat16* __restrict__ Wh = POOL ? g_W2Th : g_W1Th;
    const __nv_bfloat16* __restrict__ Wl = POOL ? g_W2Tl : g_W1Tl;

    extern __shared__ char smem_raw[];
    __nv_bfloat16* Ah = (__nv_bfloat16*)smem_raw;
    __nv_bfloat16* Al = Ah + 2 * BM * LDA;
    __nv_bfloat16* Bh = Al + 2 * BM * LDA;
    __nv_bfloat16* Bl = Bh + 2 * BK * LDB;

    const int tid = threadIdx.x;
    const int mtile = blockIdx.x;            // 0..63
    const int nBase = blockIdx.y * BN;
    const int t = mtile >> 3;
    const int rem = mtile & 7;
    const int dp = (rem >> 1) + 1;           // data slabs 1..4
    const int half = rem & 1;
    const int rowBase = (t * WINSLABS + dp) * SLAB + half * BM;

    wmma::fragment<wmma::accumulator, 16, 16, 16, float> acc[4][2];
#pragma unroll
    for (int i = 0; i < 4; i++)
#pragma unroll
        for (int j = 0; j < 2; j++) wmma::fill_fragment(acc[i][j], 0.f);

    const int warpId = tid >> 5;
    const int warpM = warpId >> 2;  // 0..1 -> 64 rows
    const int warpN = warpId & 3;   // 0..3 -> 32 cols

    auto loadTile = [&](int kt, int buf) {
        const int kidx = kt >> 5;
        const int icBase = (kt & 31) << 5;
        const int kd = kidx / 9, r9 = kidx - kd * 9;
        const int kh = r9 / 3, kw = r9 - kh * 3;
        const long off = (long)(kd - 1) * SLAB + (kh - 1) * 16 + (kw - 1);
        const long rb = (long)(rowBase + off) * CH + icBase;
        __nv_bfloat16* dAh = Ah + buf * BM * LDA;
        __nv_bfloat16* dAl = Al + buf * BM * LDA;
#pragma unroll
        for (int it = 0; it < 2; it++) {
            int v = it * 256 + tid;
            int lr = v >> 2, c8 = (v & 3) << 3;
            *(uint4*)(dAh + lr * LDA + c8) = *(const uint4*)(Xh + rb + (long)lr * CH + c8);
            *(uint4*)(dAl + lr * LDA + c8) = *(const uint4*)(Xl + rb + (long)lr * CH + c8);
        }
        const size_t wb = (size_t)kt * BK * N + nBase;
        __nv_bfloat16* dBh = Bh + buf * BK * LDB;
        __nv_bfloat16* dBl = Bl + buf * BK * LDB;
#pragma unroll
        for (int it = 0; it < 2; it++) {
            int v = it * 256 + tid;
            int row = v >> 4, c8 = (v & 15) << 3;
            *(uint4*)(dBh + row * LDB + c8) = *(const uint4*)(Wh + wb + (size_t)row * N + c8);
            *(uint4*)(dBl + row * LDB + c8) = *(const uint4*)(Wl + wb + (size_t)row * N + c8);
        }
    };

    const int KT = KDIM / BK;  // 864
    loadTile(0, 0);
    __syncthreads();

    for (int kt = 0; kt < KT; kt++) {
        const int cur = kt & 1;
        if (kt + 1 < KT) loadTile(kt + 1, cur ^ 1);
        const __nv_bfloat16* ah = Ah + cur * BM * LDA;
        const __nv_bfloat16* al = Al + cur * BM * LDA;
        const __nv_bfloat16* bh = Bh + cur * BK * LDB;
        const __nv_bfloat16* bl = Bl + cur * BK * LDB;
#pragma unroll
        for (int ks = 0; ks < 2; ks++) {
            wmma::fragment<wmma::matrix_b, 16, 16, 16, __nv_bfloat16, wmma::row_major> fbh[2], fbl[2];
#pragma unroll
            for (int j = 0; j < 2; j++) {
                wmma::load_matrix_sync(fbh[j], bh + ks * 16 * LDB + warpN * 32 + j * 16, LDB);
                wmma::load_matrix_sync(fbl[j], bl + ks * 16 * LDB + warpN * 32 + j * 16, LDB);
            }
#pragma unroll
            for (int i = 0; i < 4; i++) {
                wmma::fragment<wmma::matrix_a, 16, 16, 16, __nv_bfloat16, wmma::row_major> fah, fal;
                wmma::load_matrix_sync(fah, ah + (warpM * 64 + i * 16) * LDA + ks * 16, LDA);
                wmma::load_matrix_sync(fal, al + (warpM * 64 + i * 16) * LDA + ks * 16, LDA);
#pragma unroll
                for (int j = 0; j < 2; j++) {
                    wmma::mma_sync(acc[i][j], fah, fbh[j], acc[i][j]);
                    wmma::mma_sync(acc[i][j], fah, fbl[j], acc[i][j]);
                    wmma::mma_sync(acc[i][j], fal, fbh[j], acc[i][j]);
                }
            }
        }
        __syncthreads();
    }

    // stage accumulators
    float* Stage = (float*)smem_raw;  // 128 x LDSTG floats = 67584 B
#pragma unroll
    for (int i = 0; i < 4; i++)
#pragma unroll
        for (int j = 0; j < 2; j++)
            wmma::store_matrix_sync(Stage + (warpM * 64 + i * 16) * LDSTG + warpN * 32 + j * 16,
                                    acc[i][j], LDSTG, wmma::mem_row_major);
    __syncthreads();

    if (!POOL) {
        // bias + relu + pad-mask -> X2 hi/lo (channels-last)
        const int r = tid & 127, chunk = tid >> 7;       // chunk: 64-col half
        const int sr = half * 128 + r;
        const int hp = sr >> 4, wp = sr & 15;
        const bool valid = (hp >= 1 && hp <= 14 && wp >= 1 && wp <= 14);
        __nv_bfloat16* Yh = g_X2h + ((size_t)(GUARD + rowBase + r)) * CH + nBase + chunk * 64;
        __nv_bfloat16* Yl = g_X2l + ((size_t)(GUARD + rowBase + r)) * CH + nBase + chunk * 64;
        const float* srow = Stage + r * LDSTG + chunk * 64;
        const float* brow = bias + nBase + chunk * 64;
#pragma unroll
        for (int j = 0; j < 8; j++) {
            __nv_bfloat16 ph[8], pl[8];
#pragma unroll
            for (int e = 0; e < 8; e++) {
                float v = valid ? fmaxf(srow[j * 8 + e] + brow[j * 8 + e], 0.f) : 0.f;
                split_bf16(v, ph[e], pl[e]);
            }
            *(uint4*)(Yh + j * 8) = *(uint4*)ph;
            *(uint4*)(Yl + j * 8) = *(uint4*)pl;
        }
    } else {
        // bias + relu + maxpool over valid rows -> atomicMax
        const int col = tid & 127, rh = tid >> 7;
        float m = 0.f;
        for (int r = rh * 64; r < rh * 64 + 64; r++) {
            int sr = half * 128 + r;
            int hp = sr >> 4, wp = sr & 15;
            if (hp >= 1 && hp <= 14 && wp >= 1 && wp <= 14)
                m = fmaxf(m, Stage[r * LDSTG + col] + bias[nBase + col]);
        }
        m = fmaxf(m, 0.f);
        atomicMax((int*)&g_pooled[t * C2 + nBase + col], __float_as_int(m));
    }
}

// y[t,o] = relu(sum_i x[t,i]*W[o,i] + b[o]); warp per (t,o)
template<int IN, int OUT>
__global__ void k_fc(const float* __restrict__ W, const float* __restrict__ b,
                     const float* __restrict__ x, float* __restrict__ y) {
    int w = threadIdx.x >> 5, lane = threadIdx.x & 31;
    int o = blockIdx.x * 8 + w, t = blockIdx.y;
    float s = 0.f;
    for (int i = lane; i < IN; i += 32) s += x[t * IN + i] * W[(size_t)o * IN + i];
#pragma unroll
    for (int d = 16; d; d >>= 1) s += __shfl_down_sync(0xffffffffu, s, d);
    if (lane == 0) y[t * OUT + o] = fmaxf(s + b[o], 0.f);
}

extern "C" void kernel_launch(void* const* d_in, const int* in_sizes, int n_in,
                              void* d_out, int out_size) {
    const float* videos  = (const float*)d_in[0];
    const float* conv1_w = (const float*)d_in[1];
    const float* conv1_b = (const float*)d_in[2];
    const float* conv2_w = (const float*)d_in[3];
    const float* conv2_b = (const float*)d_in[4];
    const float* l1_w = (const float*)d_in[5];
    const float* l1_b = (const float*)d_in[6];
    const float* l2_w = (const float*)d_in[7];
    const float* l2_b = (const float*)d_in[8];
    const float* l3_w = (const float*)d_in[9];
    const float* l3_b = (const float*)d_in[10];
    float* out = (float*)d_out;

    cudaFuncSetAttribute(k_gemm<CH, false>, cudaFuncAttributeMaxDynamicSharedMemorySize, SMEM_BYTES);
    cudaFuncSetAttribute(k_gemm<C2, true>, cudaFuncAttributeMaxDynamicSharedMemorySize, SMEM_BYTES);

    __nv_bfloat16 *w1th, *w1tl, *w2th, *w2tl;
    float *pooled, *m1, *m2;
    cudaGetSymbolAddress((void**)&w1th, g_W1Th);
    cudaGetSymbolAddress((void**)&w1tl, g_W1Tl);
    cudaGetSymbolAddress((void**)&w2th, g_W2Th);
    cudaGetSymbolAddress((void**)&w2tl, g_W2Tl);
    cudaGetSymbolAddress((void**)&pooled, g_pooled);
    cudaGetSymbolAddress((void**)&m1, g_m1);
    cudaGetSymbolAddress((void**)&m2, g_m2);

    constexpr int TOT = NWIN * 4 * 14 * 14 * CH;
    k_gather<<<(TOT + 255) / 256, 256>>>(videos);
    k_transpose<CH><<<dim3(CH / 32, CH), 256>>>(conv1_w, w1th, w1tl);
    k_transpose<C2><<<dim3(C2 / 32, CH), 256>>>(conv2_w, w2th, w2tl);
    k_zero_pooled<<<(NWIN * C2 + 255) / 256, 256>>>();

    k_gemm<CH, false><<<dim3(64, CH / BN), 256, SMEM_BYTES>>>(conv1_b);
    k_gemm<C2, true><<<dim3(64, C2 / BN), 256, SMEM_BYTES>>>(conv2_b);

    k_fc<512, 512><<<dim3(64, NWIN), 256>>>(l1_w, l1_b, pooled, m1);
    k_fc<512, 512><<<dim3(64, NWIN), 256>>>(l2_w, l2_b, m1, m2);
    k_fc<512, 128><<<dim3(16, NWIN), 256>>>(l3_w, l3_b, m2, out);
}

// round 4
// speedup vs baseline: 1.0000x; 1.0000x over previous
#include <cuda_runtime.h>
#include <cuda_bf16.h>
#include <mma.h>
#include <cstdint>

using namespace nvcuda;

constexpr int NWIN = 8, CH = 1024, C2 = 512;
constexpr int SLAB = 256, WINSLABS = 6;
constexpr int ROWS_TOTAL = NWIN * WINSLABS * SLAB;      // 12288
constexpr int GUARD = SLAB;
constexpr int ROWS_ALLOC = ROWS_TOTAL + 2 * GUARD;      // 12800
constexpr int KDIM = 27 * CH;                           // 27648
constexpr int BM = 128, BN = 128, BK = 32;
constexpr int LDA = 48, LDB = 144, LDSTG = 132;
constexpr int SMEM_BYTES = (2 * BM * LDA + 2 * BK * LDB) * 2 * 2; // 86016

__device__ __nv_bfloat16 g_X1h[(size_t)ROWS_ALLOC * CH];
__device__ __nv_bfloat16 g_X1l[(size_t)ROWS_ALLOC * CH];
__device__ __nv_bfloat16 g_X2h[(size_t)ROWS_ALLOC * CH];
__device__ __nv_bfloat16 g_X2l[(size_t)ROWS_ALLOC * CH];
__device__ __nv_bfloat16 g_W1Th[(size_t)KDIM * CH];
__device__ __nv_bfloat16 g_W1Tl[(size_t)KDIM * CH];
__device__ __nv_bfloat16 g_W2Th[(size_t)KDIM * C2];
__device__ __nv_bfloat16 g_W2Tl[(size_t)KDIM * C2];
__device__ float g_pooled[NWIN * C2];
__device__ float g_m1[NWIN * 512];
__device__ float g_m2[NWIN * 512];

__device__ __forceinline__ void split_bf16(float v, __nv_bfloat16& hi, __nv_bfloat16& lo) {
    hi = __float2bfloat16(v);
    lo = __float2bfloat16(v - __bfloat162float(hi));
}

__global__ void k_zero_pooled() {
    int i = blockIdx.x * 256 + threadIdx.x;
    if (i < NWIN * C2) g_pooled[i] = 0.f;
}

// videos (1,8,1024,14,14) -> padded channels-last windows, hi/lo split
__global__ void k_gather(const float* __restrict__ videos) {
    int i = blockIdx.x * 256 + threadIdx.x;
    constexpr int TOT = NWIN * 4 * 14 * 14 * CH;
    if (i >= TOT) return;
    int c = i & (CH - 1);
    int rest = i >> 10;
    int w = rest % 14; rest /= 14;
    int h = rest % 14; rest /= 14;
    int d = rest & 3;
    int t = rest >> 2;
    int frame = t - 4 + d;  // window t holds frames t-4..t-1 (zeros before 0)
    float v = (frame >= 0) ? videos[(size_t)(frame * CH + c) * 196 + h * 14 + w] : 0.f;
    __nv_bfloat16 hi, lo; split_bf16(v, hi, lo);
    size_t dst = (size_t)(GUARD + (t * WINSLABS + d + 1) * SLAB + (h + 1) * 16 + (w + 1)) * CH + c;
    g_X1h[dst] = hi;
    g_X1l[dst] = lo;
}

// conv weights (oc, ic, 27) -> WT[kidx*CH+ic][oc] hi/lo
template<int NOC>
__global__ void k_transpose(const float* __restrict__ w,
                            __nv_bfloat16* __restrict__ wth,
                            __nv_bfloat16* __restrict__ wtl) {
    __shared__ float s[32][28];
    int ocBase = blockIdx.x * 32;
    int ic = blockIdx.y;
    for (int idx = threadIdx.x; idx < 32 * 27; idx += 256) {
        int oc = idx / 27, kk = idx - oc * 27;
        s[oc][kk] = w[((size_t)(ocBase + oc) * CH + ic) * 27 + kk];
    }
    __syncthreads();
    for (int idx = threadIdx.x; idx < 27 * 32; idx += 256) {
        int kk = idx >> 5, oc = idx & 31;
        __nv_bfloat16 hi, lo; split_bf16(s[oc][kk], hi, lo);
        size_t o = ((size_t)kk * CH + ic) * NOC + ocBase + oc;
        wth[o] = hi;
        wtl[o] = lo;
    }
}

// Implicit-conv GEMM, bf16 hi/lo 3-term, 128x128x32 tiles, 8 warps.
template<int N, bool POOL>
__global__ void __launch_bounds__(256)
k_gemm(const float* __restrict__ bias) {
    const __nv_bfloat16* __restrict__ Xh = (POOL ? g_X2h : g_X1h) + (size_t)GUARD * CH;
    const __nv_bfloat16* __restrict__ Xl = (POOL ? g_X2l : g_X1l) + (size_t)GUARD * CH;
    const __nv_bfloat16* __restrict__ Wh = POOL ? g_W2Th : g_W1Th;
    const __nv_bfloat16* __restrict__ Wl = POOL ? g_W2Tl : g_W1Tl;

    extern __shared__ char smem_raw[];
    __nv_bfloat16* Ah = (__nv_bfloat16*)smem_raw;
    __nv_bfloat16* Al = Ah + 2 * BM * LDA;
    __nv_bfloat16* Bh = Al + 2 * BM * LDA;
    __nv_bfloat16* Bl = Bh + 2 * BK * LDB;

    const int tid = threadIdx.x;
    const int mtile = blockIdx.x;            // 0..63
    const int nBase = blockIdx.y * BN;
    const int t = mtile >> 3;
    const int rem = mtile & 7;
    const int dp = (rem >> 1) + 1;           // data slabs 1..4
    const int half = rem & 1;
    const int rowBase = (t * WINSLABS + dp) * SLAB + half * BM;

    wmma::fragment<wmma::accumulator, 16, 16, 16, float> acc[4][2];
#pragma unroll
    for (int i = 0; i < 4; i++)
#pragma unroll
        for (int j = 0; j < 2; j++) wmma::fill_fragment(acc[i][j], 0.f);

    const int warpId = tid >> 5;
    const int warpM = warpId >> 2;  // 0..1 -> 64 rows
    const int warpN = warpId & 3;   // 0..3 -> 32 cols

    auto loadTile = [&](int kt, int buf) {
        const int kidx = kt >> 5;
        const int icBase = (kt & 31) << 5;
        const int kd = kidx / 9, r9 = kidx - kd * 9;
        const int kh = r9 / 3, kw = r9 - kh * 3;
        const long off = (long)(kd - 1) * SLAB + (kh - 1) * 16 + (kw - 1);
        const long rb = (long)(rowBase + off) * CH + icBase;
        __nv_bfloat16* dAh = Ah + buf * BM * LDA;
        __nv_bfloat16* dAl = Al + buf * BM * LDA;
#pragma unroll
        for (int it = 0; it < 2; it++) {
            int v = it * 256 + tid;
            int lr = v >> 2, c8 = (v & 3) << 3;
            *(uint4*)(dAh + lr * LDA + c8) = *(const uint4*)(Xh + rb + (long)lr * CH + c8);
            *(uint4*)(dAl + lr * LDA + c8) = *(const uint4*)(Xl + rb + (long)lr * CH + c8);
        }
        const size_t wb = (size_t)kt * BK * N + nBase;
        __nv_bfloat16* dBh = Bh + buf * BK * LDB;
        __nv_bfloat16* dBl = Bl + buf * BK * LDB;
#pragma unroll
        for (int it = 0; it < 2; it++) {
            int v = it * 256 + tid;
            int row = v >> 4, c8 = (v & 15) << 3;
            *(uint4*)(dBh + row * LDB + c8) = *(const uint4*)(Wh + wb + (size_t)row * N + c8);
            *(uint4*)(dBl + row * LDB + c8) = *(const uint4*)(Wl + wb + (size_t)row * N + c8);
        }
    };

    const int KT = KDIM / BK;  // 864
    loadTile(0, 0);
    __syncthreads();

    for (int kt = 0; kt < KT; kt++) {
        const int cur = kt & 1;
        if (kt + 1 < KT) loadTile(kt + 1, cur ^ 1);
        const __nv_bfloat16* ah = Ah + cur * BM * LDA;
        const __nv_bfloat16* al = Al + cur * BM * LDA;
        const __nv_bfloat16* bh = Bh + cur * BK * LDB;
        const __nv_bfloat16* bl = Bl + cur * BK * LDB;
#pragma unroll
        for (int ks = 0; ks < 2; ks++) {
            wmma::fragment<wmma::matrix_b, 16, 16, 16, __nv_bfloat16, wmma::row_major> fbh[2], fbl[2];
#pragma unroll
            for (int j = 0; j < 2; j++) {
                wmma::load_matrix_sync(fbh[j], bh + ks * 16 * LDB + warpN * 32 + j * 16, LDB);
                wmma::load_matrix_sync(fbl[j], bl + ks * 16 * LDB + warpN * 32 + j * 16, LDB);
            }
#pragma unroll
            for (int i = 0; i < 4; i++) {
                wmma::fragment<wmma::matrix_a, 16, 16, 16, __nv_bfloat16, wmma::row_major> fah, fal;
                wmma::load_matrix_sync(fah, ah + (warpM * 64 + i * 16) * LDA + ks * 16, LDA);
                wmma::load_matrix_sync(fal, al + (warpM * 64 + i * 16) * LDA + ks * 16, LDA);
#pragma unroll
                for (int j = 0; j < 2; j++) {
                    wmma::mma_sync(acc[i][j], fah, fbh[j], acc[i][j]);
                    wmma::mma_sync(acc[i][j], fah, fbl[j], acc[i][j]);
                    wmma::mma_sync(acc[i][j], fal, fbh[j], acc[i][j]);
                }
            }
        }
        __syncthreads();
    }

    // stage accumulators
    float* Stage = (float*)smem_raw;  // 128 x LDSTG floats = 67584 B
#pragma unroll
    for (int i = 0; i < 4; i++)
#pragma unroll
        for (int j = 0; j < 2; j++)
            wmma::store_matrix_sync(Stage + (warpM * 64 + i * 16) * LDSTG + warpN * 32 + j * 16,
                                    acc[i][j], LDSTG, wmma::mem_row_major);
    __syncthreads();

    if (!POOL) {
        // bias + relu + pad-mask -> X2 hi/lo (channels-last)
        const int r = tid & 127, chunk = tid >> 7;       // chunk: 64-col half
        const int sr = half * 128 + r;
        const int hp = sr >> 4, wp = sr & 15;
        const bool valid = (hp >= 1 && hp <= 14 && wp >= 1 && wp <= 14);
        __nv_bfloat16* Yh = g_X2h + ((size_t)(GUARD + rowBase + r)) * CH + nBase + chunk * 64;
        __nv_bfloat16* Yl = g_X2l + ((size_t)(GUARD + rowBase + r)) * CH + nBase + chunk * 64;
        const float* srow = Stage + r * LDSTG + chunk * 64;
        const float* brow = bias + nBase + chunk * 64;
#pragma unroll
        for (int j = 0; j < 8; j++) {
            __nv_bfloat16 ph[8], pl[8];
#pragma unroll
            for (int e = 0; e < 8; e++) {
                float v = valid ? fmaxf(srow[j * 8 + e] + brow[j * 8 + e], 0.f) : 0.f;
                split_bf16(v, ph[e], pl[e]);
            }
            *(uint4*)(Yh + j * 8) = *(uint4*)ph;
            *(uint4*)(Yl + j * 8) = *(uint4*)pl;
        }
    } else {
        // bias + relu + maxpool over valid rows -> atomicMax
        const int col = tid & 127, rh = tid >> 7;
        float m = 0.f;
        for (int r = rh * 64; r < rh * 64 + 64; r++) {
            int sr = half * 128 + r;
            int hp = sr >> 4, wp = sr & 15;
            if (hp >= 1 && hp <= 14 && wp >= 1 && wp <= 14)
                m = fmaxf(m, Stage[r * LDSTG + col] + bias[nBase + col]);
        }
        m = fmaxf(m, 0.f);
        atomicMax((int*)&g_pooled[t * C2 + nBase + col], __float_as_int(m));
    }
}

// y[t,o] = relu(sum_i x[t,i]*W[o,i] + b[o]); warp per (t,o)
template<int IN, int OUT>
__global__ void k_fc(const float* __restrict__ W, const float* __restrict__ b,
                     const float* __restrict__ x, float* __restrict__ y) {
    int w = threadIdx.x >> 5, lane = threadIdx.x & 31;
    int o = blockIdx.x * 8 + w, t = blockIdx.y;
    float s = 0.f;
    for (int i = lane; i < IN; i += 32) s += x[t * IN + i] * W[(size_t)o * IN + i];
#pragma unroll
    for (int d = 16; d; d >>= 1) s += __shfl_down_sync(0xffffffffu, s, d);
    if (lane == 0) y[t * OUT + o] = fmaxf(s + b[o], 0.f);
}

extern "C" void kernel_launch(void* const* d_in, const int* in_sizes, int n_in,
                              void* d_out, int out_size) {
    const float* videos  = (const float*)d_in[0];
    const float* conv1_w = (const float*)d_in[1];
    const float* conv1_b = (const float*)d_in[2];
    const float* conv2_w = (const float*)d_in[3];
    const float* conv2_b = (const float*)d_in[4];
    const float* l1_w = (const float*)d_in[5];
    const float* l1_b = (const float*)d_in[6];
    const float* l2_w = (const float*)d_in[7];
    const float* l2_b = (const float*)d_in[8];
    const float* l3_w = (const float*)d_in[9];
    const float* l3_b = (const float*)d_in[10];
    float* out = (float*)d_out;

    cudaFuncSetAttribute(k_gemm<CH, false>, cudaFuncAttributeMaxDynamicSharedMemorySize, SMEM_BYTES);
    cudaFuncSetAttribute(k_gemm<C2, true>, cudaFuncAttributeMaxDynamicSharedMemorySize, SMEM_BYTES);

    __nv_bfloat16 *w1th, *w1tl, *w2th, *w2tl;
    float *pooled, *m1, *m2;
    cudaGetSymbolAddress((void**)&w1th, g_W1Th);
    cudaGetSymbolAddress((void**)&w1tl, g_W1Tl);
    cudaGetSymbolAddress((void**)&w2th, g_W2Th);
    cudaGetSymbolAddress((void**)&w2tl, g_W2Tl);
    cudaGetSymbolAddress((void**)&pooled, g_pooled);
    cudaGetSymbolAddress((void**)&m1, g_m1);
    cudaGetSymbolAddress((void**)&m2, g_m2);

    constexpr int TOT = NWIN * 4 * 14 * 14 * CH;
    k_gather<<<(TOT + 255) / 256, 256>>>(videos);
    k_transpose<CH><<<dim3(CH / 32, CH), 256>>>(conv1_w, w1th, w1tl);
    k_transpose<C2><<<dim3(C2 / 32, CH), 256>>>(conv2_w, w2th, w2tl);
    k_zero_pooled<<<(NWIN * C2 + 255) / 256, 256>>>();

    k_gemm<CH, false><<<dim3(64, CH / BN), 256, SMEM_BYTES>>>(conv1_b);
    k_gemm<C2, true><<<dim3(64, C2 / BN), 256, SMEM_BYTES>>>(conv2_b);

    k_fc<512, 512><<<dim3(64, NWIN), 256>>>(l1_w, l1_b, pooled, m1);
    k_fc<512, 512><<<dim3(64, NWIN), 256>>>(l2_w, l2_b, m1, m2);
    k_fc<512, 128><<<dim3(16, NWIN), 256>>>(l3_w, l3_b, m2, out);
}

// round 5
// speedup vs baseline: 1.0005x; 1.0005x over previous
#include <cuda_runtime.h>
#include <cuda_bf16.h>
#include <mma.h>
#include <cstdint>

using namespace nvcuda;

constexpr int NWIN = 8, CH = 1024, C2 = 512;
constexpr int SLAB = 256, WINSLABS = 6;
constexpr int ROWS_TOTAL = NWIN * WINSLABS * SLAB;      // 12288
constexpr int GUARD = SLAB;
constexpr int ROWS_ALLOC = ROWS_TOTAL + 2 * GUARD;      // 12800
constexpr int KDIM = 27 * CH;                           // 27648
constexpr int BM = 128, BN = 128, BK = 32;
constexpr int LDA = 48, LDB = 144, LDSTG = 132;
constexpr int SMEM_BYTES = (2 * BM * LDA + 2 * BK * LDB) * 2 * 2; // 86016

__device__ __nv_bfloat16 g_X1h[(size_t)ROWS_ALLOC * CH];
__device__ __nv_bfloat16 g_X1l[(size_t)ROWS_ALLOC * CH];
__device__ __nv_bfloat16 g_X2h[(size_t)ROWS_ALLOC * CH];
__device__ __nv_bfloat16 g_X2l[(size_t)ROWS_ALLOC * CH];
__device__ __nv_bfloat16 g_W1Th[(size_t)KDIM * CH];
__device__ __nv_bfloat16 g_W1Tl[(size_t)KDIM * CH];
__device__ __nv_bfloat16 g_W2Th[(size_t)KDIM * C2];
__device__ __nv_bfloat16 g_W2Tl[(size_t)KDIM * C2];
__device__ float g_pooled[NWIN * C2];
__device__ float g_m1[NWIN * 512];
__device__ float g_m2[NWIN * 512];

__device__ __forceinline__ void split_bf16(float v, __nv_bfloat16& hi, __nv_bfloat16& lo) {
    hi = __float2bfloat16(v);
    lo = __float2bfloat16(v - __bfloat162float(hi));
}

__global__ void k_zero_pooled() {
    int i = blockIdx.x * 256 + threadIdx.x;
    if (i < NWIN * C2) g_pooled[i] = 0.f;
}

// videos (1,8,1024,14,14) -> padded channels-last windows, hi/lo split
__global__ void k_gather(const float* __restrict__ videos) {
    int i = blockIdx.x * 256 + threadIdx.x;
    constexpr int TOT = NWIN * 4 * 14 * 14 * CH;
    if (i >= TOT) return;
    int c = i & (CH - 1);
    int rest = i >> 10;
    int w = rest % 14; rest /= 14;
    int h = rest % 14; rest /= 14;
    int d = rest & 3;
    int t = rest >> 2;
    int frame = t - 4 + d;  // window t holds frames t-4..t-1 (zeros before 0)
    float v = (frame >= 0) ? videos[(size_t)(frame * CH + c) * 196 + h * 14 + w] : 0.f;
    __nv_bfloat16 hi, lo; split_bf16(v, hi, lo);
    size_t dst = (size_t)(GUARD + (t * WINSLABS + d + 1) * SLAB + (h + 1) * 16 + (w + 1)) * CH + c;
    g_X1h[dst] = hi;
    g_X1l[dst] = lo;
}

// conv weights (oc, ic, 27) -> WT[kidx*CH+ic][oc] hi/lo
template<int NOC>
__global__ void k_transpose(const float* __restrict__ w,
                            __nv_bfloat16* __restrict__ wth,
                            __nv_bfloat16* __restrict__ wtl) {
    __shared__ float s[32][28];
    int ocBase = blockIdx.x * 32;
    int ic = blockIdx.y;
    for (int idx = threadIdx.x; idx < 32 * 27; idx += 256) {
        int oc = idx / 27, kk = idx - oc * 27;
        s[oc][kk] = w[((size_t)(ocBase + oc) * CH + ic) * 27 + kk];
    }
    __syncthreads();
    for (int idx = threadIdx.x; idx < 27 * 32; idx += 256) {
        int kk = idx >> 5, oc = idx & 31;
        __nv_bfloat16 hi, lo; split_bf16(s[oc][kk], hi, lo);
        size_t o = ((size_t)kk * CH + ic) * NOC + ocBase + oc;
        wth[o] = hi;
        wtl[o] = lo;
    }
}

// Implicit-conv GEMM, bf16 hi/lo 3-term, 128x128x32 tiles, 8 warps.
template<int N, bool POOL>
__global__ void __launch_bounds__(256)
k_gemm(const float* __restrict__ bias) {
    const __nv_bfloat16* __restrict__ Xh = (POOL ? g_X2h : g_X1h) + (size_t)GUARD * CH;
    const __nv_bfloat16* __restrict__ Xl = (POOL ? g_X2l : g_X1l) + (size_t)GUARD * CH;
    const __nv_bfloat16* __restrict__ Wh = POOL ? g_W2Th : g_W1Th;
    const __nv_bfloat16* __restrict__ Wl = POOL ? g_W2Tl : g_W1Tl;

    extern __shared__ char smem_raw[];
    __nv_bfloat16* Ah = (__nv_bfloat16*)smem_raw;
    __nv_bfloat16* Al = Ah + 2 * BM * LDA;
    __nv_bfloat16* Bh = Al + 2 * BM * LDA;
    __nv_bfloat16* Bl = Bh + 2 * BK * LDB;

    const int tid = threadIdx.x;
    const int mtile = blockIdx.x;            // 0..63
    const int nBase = blockIdx.y * BN;
    const int t = mtile >> 3;
    const int rem = mtile & 7;
    const int dp = (rem >> 1) + 1;           // data slabs 1..4
    const int half = rem & 1;
    const int rowBase = (t * WINSLABS + dp) * SLAB + half * BM;

    wmma::fragment<wmma::accumulator, 16, 16, 16, float> acc[4][2];
#pragma unroll
    for (int i = 0; i < 4; i++)
#pragma unroll
        for (int j = 0; j < 2; j++) wmma::fill_fragment(acc[i][j], 0.f);

    const int warpId = tid >> 5;
    const int warpM = warpId >> 2;  // 0..1 -> 64 rows
    const int warpN = warpId & 3;   // 0..3 -> 32 cols

    auto loadTile = [&](int kt, int buf) {
        const int kidx = kt >> 5;
        const int icBase = (kt & 31) << 5;
        const int kd = kidx / 9, r9 = kidx - kd * 9;
        const int kh = r9 / 3, kw = r9 - kh * 3;
        const long off = (long)(kd - 1) * SLAB + (kh - 1) * 16 + (kw - 1);
        const long rb = (long)(rowBase + off) * CH + icBase;
        __nv_bfloat16* dAh = Ah + buf * BM * LDA;
        __nv_bfloat16* dAl = Al + buf * BM * LDA;
#pragma unroll
        for (int it = 0; it < 2; it++) {
            int v = it * 256 + tid;
            int lr = v >> 2, c8 = (v & 3) << 3;
            *(uint4*)(dAh + lr * LDA + c8) = *(const uint4*)(Xh + rb + (long)lr * CH + c8);
            *(uint4*)(dAl + lr * LDA + c8) = *(const uint4*)(Xl + rb + (long)lr * CH + c8);
        }
        const size_t wb = (size_t)kt * BK * N + nBase;
        __nv_bfloat16* dBh = Bh + buf * BK * LDB;
        __nv_bfloat16* dBl = Bl + buf * BK * LDB;
#pragma unroll
        for (int it = 0; it < 2; it++) {
            int v = it * 256 + tid;
            int row = v >> 4, c8 = (v & 15) << 3;
            *(uint4*)(dBh + row * LDB + c8) = *(const uint4*)(Wh + wb + (size_t)row * N + c8);
            *(uint4*)(dBl + row * LDB + c8) = *(const uint4*)(Wl + wb + (size_t)row * N + c8);
        }
    };

    const int KT = KDIM / BK;  // 864
    loadTile(0, 0);
    __syncthreads();

    for (int kt = 0; kt < KT; kt++) {
        const int cur = kt & 1;
        if (kt + 1 < KT) loadTile(kt + 1, cur ^ 1);
        const __nv_bfloat16* ah = Ah + cur * BM * LDA;
        const __nv_bfloat16* al = Al + cur * BM * LDA;
        const __nv_bfloat16* bh = Bh + cur * BK * LDB;
        const __nv_bfloat16* bl = Bl + cur * BK * LDB;
#pragma unroll
        for (int ks = 0; ks < 2; ks++) {
            wmma::fragment<wmma::matrix_b, 16, 16, 16, __nv_bfloat16, wmma::row_major> fbh[2], fbl[2];
#pragma unroll
            for (int j = 0; j < 2; j++) {
                wmma::load_matrix_sync(fbh[j], bh + ks * 16 * LDB + warpN * 32 + j * 16, LDB);
                wmma::load_matrix_sync(fbl[j], bl + ks * 16 * LDB + warpN * 32 + j * 16, LDB);
            }
#pragma unroll
            for (int i = 0; i < 4; i++) {
                wmma::fragment<wmma::matrix_a, 16, 16, 16, __nv_bfloat16, wmma::row_major> fah, fal;
                wmma::load_matrix_sync(fah, ah + (warpM * 64 + i * 16) * LDA + ks * 16, LDA);
                wmma::load_matrix_sync(fal, al + (warpM * 64 + i * 16) * LDA + ks * 16, LDA);
#pragma unroll
                for (int j = 0; j < 2; j++) {
                    wmma::mma_sync(acc[i][j], fah, fbh[j], acc[i][j]);
                    wmma::mma_sync(acc[i][j], fah, fbl[j], acc[i][j]);
                    wmma::mma_sync(acc[i][j], fal, fbh[j], acc[i][j]);
                }
            }
        }
        __syncthreads();
    }

    // stage accumulators
    float* Stage = (float*)smem_raw;  // 128 x LDSTG floats = 67584 B
#pragma unroll
    for (int i = 0; i < 4; i++)
#pragma unroll
        for (int j = 0; j < 2; j++)
            wmma::store_matrix_sync(Stage + (warpM * 64 + i * 16) * LDSTG + warpN * 32 + j * 16,
                                    acc[i][j], LDSTG, wmma::mem_row_major);
    __syncthreads();

    if (!POOL) {
        // bias + relu + pad-mask -> X2 hi/lo (channels-last)
        const int r = tid & 127, chunk = tid >> 7;       // chunk: 64-col half
        const int sr = half * 128 + r;
        const int hp = sr >> 4, wp = sr & 15;
        const bool valid = (hp >= 1 && hp <= 14 && wp >= 1 && wp <= 14);
        __nv_bfloat16* Yh = g_X2h + ((size_t)(GUARD + rowBase + r)) * CH + nBase + chunk * 64;
        __nv_bfloat16* Yl = g_X2l + ((size_t)(GUARD + rowBase + r)) * CH + nBase + chunk * 64;
        const float* srow = Stage + r * LDSTG + chunk * 64;
        const float* brow = bias + nBase + chunk * 64;
#pragma unroll
        for (int j = 0; j < 8; j++) {
            __nv_bfloat16 ph[8], pl[8];
#pragma unroll
            for (int e = 0; e < 8; e++) {
                float v = valid ? fmaxf(srow[j * 8 + e] + brow[j * 8 + e], 0.f) : 0.f;
                split_bf16(v, ph[e], pl[e]);
            }
            *(uint4*)(Yh + j * 8) = *(uint4*)ph;
            *(uint4*)(Yl + j * 8) = *(uint4*)pl;
        }
    } else {
        // bias + relu + maxpool over valid rows -> atomicMax
        const int col = tid & 127, rh = tid >> 7;
        float m = 0.f;
        for (int r = rh * 64; r < rh * 64 + 64; r++) {
            int sr = half * 128 + r;
            int hp = sr >> 4, wp = sr & 15;
            if (hp >= 1 && hp <= 14 && wp >= 1 && wp <= 14)
                m = fmaxf(m, Stage[r * LDSTG + col] + bias[nBase + col]);
        }
        m = fmaxf(m, 0.f);
        atomicMax((int*)&g_pooled[t * C2 + nBase + col], __float_as_int(m));
    }
}

// y[t,o] = relu(sum_i x[t,i]*W[o,i] + b[o]); warp per (t,o)
template<int IN, int OUT>
__global__ void k_fc(const float* __restrict__ W, const float* __restrict__ b,
                     const float* __restrict__ x, float* __restrict__ y) {
    int w = threadIdx.x >> 5, lane = threadIdx.x & 31;
    int o = blockIdx.x * 8 + w, t = blockIdx.y;
    float s = 0.f;
    for (int i = lane; i < IN; i += 32) s += x[t * IN + i] * W[(size_t)o * IN + i];
#pragma unroll
    for (int d = 16; d; d >>= 1) s += __shfl_down_sync(0xffffffffu, s, d);
    if (lane == 0) y[t * OUT + o] = fmaxf(s + b[o], 0.f);
}

extern "C" void kernel_launch(void* const* d_in, const int* in_sizes, int n_in,
                              void* d_out, int out_size) {
    const float* videos  = (const float*)d_in[0];
    const float* conv1_w = (const float*)d_in[1];
    const float* conv1_b = (const float*)d_in[2];
    const float* conv2_w = (const float*)d_in[3];
    const float* conv2_b = (const float*)d_in[4];
    const float* l1_w = (const float*)d_in[5];
    const float* l1_b = (const float*)d_in[6];
    const float* l2_w = (const float*)d_in[7];
    const float* l2_b = (const float*)d_in[8];
    const float* l3_w = (const float*)d_in[9];
    const float* l3_b = (const float*)d_in[10];
    float* out = (float*)d_out;

    cudaFuncSetAttribute(k_gemm<CH, false>, cudaFuncAttributeMaxDynamicSharedMemorySize, SMEM_BYTES);
    cudaFuncSetAttribute(k_gemm<C2, true>, cudaFuncAttributeMaxDynamicSharedMemorySize, SMEM_BYTES);

    __nv_bfloat16 *w1th, *w1tl, *w2th, *w2tl;
    float *pooled, *m1, *m2;
    cudaGetSymbolAddress((void**)&w1th, g_W1Th);
    cudaGetSymbolAddress((void**)&w1tl, g_W1Tl);
    cudaGetSymbolAddress((void**)&w2th, g_W2Th);
    cudaGetSymbolAddress((void**)&w2tl, g_W2Tl);
    cudaGetSymbolAddress((void**)&pooled, g_pooled);
    cudaGetSymbolAddress((void**)&m1, g_m1);
    cudaGetSymbolAddress((void**)&m2, g_m2);

    constexpr int TOT = NWIN * 4 * 14 * 14 * CH;
    k_gather<<<(TOT + 255) / 256, 256>>>(videos);
    k_transpose<CH><<<dim3(CH / 32, CH), 256>>>(conv1_w, w1th, w1tl);
    k_transpose<C2><<<dim3(C2 / 32, CH), 256>>>(conv2_w, w2th, w2tl);
    k_zero_pooled<<<(NWIN * C2 + 255) / 256, 256>>>();

    k_gemm<CH, false><<<dim3(64, CH / BN), 256, SMEM_BYTES>>>(conv1_b);
    k_gemm<C2, true><<<dim3(64, C2 / BN), 256, SMEM_BYTES>>>(conv2_b);

    k_fc<512, 512><<<dim3(64, NWIN), 256>>>(l1_w, l1_b, pooled, m1);
    k_fc<512, 512><<<dim3(64, NWIN), 256>>>(l2_w, l2_b, m1, m2);
    k_fc<512, 128><<<dim3(16, NWIN), 256>>>(l3_w, l3_b, m2, out);
}